// round 11
// baseline (speedup 1.0000x reference)
#include <cuda_runtime.h>
#include <cuda_bf16.h>
#include <cstdint>
#include <cstddef>

#define SQ 4096
#define DI 1024
#define HD 1024

using bf16 = __nv_bfloat16;

// ---------------- device scratch (allocation-free rule) --------------------
__device__ __align__(16) bf16 g_qh[SQ * DI], g_ql[SQ * DI];
__device__ __align__(16) bf16 g_kh[SQ * DI], g_kl[SQ * DI];
__device__ __align__(16) bf16 g_vh[SQ * DI], g_vl[SQ * DI];
__device__ __align__(16) bf16 g_wqh[DI * HD], g_wql[DI * HD];
__device__ __align__(16) bf16 g_wkh[DI * HD], g_wkl[DI * HD];
__device__ __align__(16) bf16 g_wvh[DI * HD], g_wvl[DI * HD];
__device__ __align__(16) bf16 g_Qh[SQ * HD], g_Ql[SQ * HD];
__device__ __align__(16) bf16 g_Kh[SQ * HD], g_Kl[SQ * HD];
__device__ __align__(16) bf16 g_Vth[HD * SQ], g_Vtl[HD * SQ];   // V transposed
__device__ __align__(16) float g_S[(size_t)SQ * SQ];
__device__ __align__(16) bf16 g_Ph[(size_t)SQ * SQ], g_Pl[(size_t)SQ * SQ];

// ---------------- helpers ---------------------------------------------------
__device__ __forceinline__ uint32_t smem_u32(const void* p) {
    uint32_t a;
    asm("{ .reg .u64 t; cvta.to.shared.u64 t, %1; cvt.u32.u64 %0, t; }"
        : "=r"(a) : "l"(p));
    return a;
}

__device__ __forceinline__ void cp16(uint32_t dst, const void* src) {
    asm volatile("cp.async.cg.shared.global [%0], [%1], 16;"
                 :: "r"(dst), "l"(src));
}
__device__ __forceinline__ void cp_commit() {
    asm volatile("cp.async.commit_group;");
}
template <int N>
__device__ __forceinline__ void cp_wait() {
    asm volatile("cp.async.wait_group %0;" :: "n"(N));
}

__device__ __forceinline__ void ldsm4(uint32_t& r0, uint32_t& r1, uint32_t& r2,
                                      uint32_t& r3, uint32_t addr) {
    asm volatile(
        "ldmatrix.sync.aligned.m8n8.x4.shared.b16 {%0,%1,%2,%3}, [%4];"
        : "=r"(r0), "=r"(r1), "=r"(r2), "=r"(r3) : "r"(addr));
}

__device__ __forceinline__ void mma16816(float* c, const uint32_t* a,
                                         const uint32_t* b) {
    asm volatile(
        "mma.sync.aligned.m16n8k16.row.col.f32.bf16.bf16.f32 "
        "{%0,%1,%2,%3}, {%4,%5,%6,%7}, {%8,%9}, {%0,%1,%2,%3};"
        : "+f"(c[0]), "+f"(c[1]), "+f"(c[2]), "+f"(c[3])
        : "r"(a[0]), "r"(a[1]), "r"(a[2]), "r"(a[3]), "r"(b[0]), "r"(b[1]));
}

__device__ __forceinline__ void split_pack2(float a, float b, uint32_t& h,
                                            uint32_t& l) {
    bf16 ha = __float2bfloat16_rn(a);
    bf16 hb = __float2bfloat16_rn(b);
    bf16 la = __float2bfloat16_rn(a - __bfloat162float(ha));
    bf16 lb = __float2bfloat16_rn(b - __bfloat162float(hb));
    h = ((uint32_t)__bfloat16_as_ushort(hb) << 16) | __bfloat16_as_ushort(ha);
    l = ((uint32_t)__bfloat16_as_ushort(lb) << 16) | __bfloat16_as_ushort(la);
}

// ---------------------------------------------------------------------------
// D[128x128] = sum over 3 segments {(Ah,Bh),(Al,Bh),(Ah,Bl)} of A*B^T
// A: [M,Ktot] bf16 row-major (K contiguous). B: [N,Ktot] bf16 row-major.
// BK=64, THREE-stage circular cp.async pipeline, ONE __syncthreads per
// iteration (CUTLASS multistage order), register-double-buffered ldmatrix
// fragments, __launch_bounds__(256,2): 2 CTAs/SM (regs<=128, smem 108KB).
// EPI: 0 = bias + hi/lo split, row-major   1 = bias + split, transposed [h][s]
//      2 = fp32 * alpha                    3 = fp32
// ---------------------------------------------------------------------------
static constexpr int TILE = 18432;               // 128*72*2 bytes, one operand
static constexpr int STAGE = 2 * TILE;           // A + B per stage
static constexpr int SMEM_DYN = 3 * STAGE;       // 110592

template <int EPI>
__device__ __forceinline__ void gemm_body(
    const bf16* __restrict__ Ah, const bf16* __restrict__ Al,
    const bf16* __restrict__ Bh, const bf16* __restrict__ Bl,
    const float* __restrict__ bias, float* __restrict__ outF,
    bf16* __restrict__ outH, bf16* __restrict__ outL, int Ktot, int Nstride,
    float alpha) {
    extern __shared__ char smem[];
    const uint32_t sBase = smem_u32(smem);

    const int tid = threadIdx.x;
    const int lane = tid & 31, wid = tid >> 5;
    const int wm = (wid >> 2) << 6;   // 0,64
    const int wn = (wid & 3) << 5;    // 0,32,64,96
    const int m0 = blockIdx.y << 7, n0 = blockIdx.x << 7;

    float c[4][4][4];
#pragma unroll
    for (int i = 0; i < 4; i++)
#pragma unroll
        for (int j = 0; j < 4; j++)
#pragma unroll
            for (int q = 0; q < 4; q++) c[i][j][q] = 0.0f;

    const int T = Ktot >> 6, TT = 3 * T;
    const bf16* Asrc[3] = {Ah, Al, Ah};
    const bf16* Bsrc[3] = {Bh, Bh, Bl};

    const int lrow = tid >> 3;              // 0..31
    const int lc = (tid & 7) << 3;          // element col 0..56

    auto issue = [&](int tt, int st) {
        const int seg = (tt >= 2 * T) ? 2 : (tt >= T ? 1 : 0);
        const int kt = tt - seg * T;
        const bf16* Ab =
            Asrc[seg] + (size_t)(m0 + lrow) * Ktot + (kt << 6) + lc;
        const bf16* Bb =
            Bsrc[seg] + (size_t)(n0 + lrow) * Ktot + (kt << 6) + lc;
        const uint32_t da = sBase + st * STAGE + (lrow * 72 + lc) * 2;
        const uint32_t db = da + TILE;
#pragma unroll
        for (int i = 0; i < 4; i++) {
            cp16(da + i * (32 * 144), Ab + (size_t)(i * 32) * Ktot);
            cp16(db + i * (32 * 144), Bb + (size_t)(i * 32) * Ktot);
        }
    };

    // ldmatrix per-lane base offsets (bytes)
    const uint32_t aOff =
        ((wm + (lane & 15)) * 72 + ((lane >> 4) << 3)) * 2;
    const uint32_t bOff =
        ((wn + (lane & 7) + ((lane >> 4) << 3)) * 72 +
         (((lane >> 3) & 1) << 3)) * 2;

    auto ldfrags = [&](uint32_t sAb, uint32_t sBb, int kk, uint32_t (*a)[4],
                       uint32_t (*b)[2]) {
#pragma unroll
        for (int mi = 0; mi < 4; mi++)
            ldsm4(a[mi][0], a[mi][1], a[mi][2], a[mi][3],
                  sAb + (mi * 16 * 72 + kk * 16) * 2);
#pragma unroll
        for (int j = 0; j < 2; j++) {
            uint32_t r0, r1, r2, r3;
            ldsm4(r0, r1, r2, r3, sBb + (j * 16 * 72 + kk * 16) * 2);
            b[2 * j][0] = r0; b[2 * j][1] = r1;
            b[2 * j + 1][0] = r2; b[2 * j + 1][1] = r3;
        }
    };

    auto compute = [&](int st) {
        const uint32_t sAb = sBase + st * STAGE + aOff;
        const uint32_t sBb = sBase + st * STAGE + TILE + bOff;
        uint32_t a[2][4][4], b[2][4][2];
        ldfrags(sAb, sBb, 0, a[0], b[0]);
#pragma unroll
        for (int kk = 0; kk < 4; kk++) {
            const int cur = kk & 1;
            if (kk < 3) ldfrags(sAb, sBb, kk + 1, a[cur ^ 1], b[cur ^ 1]);
#pragma unroll
            for (int mi = 0; mi < 4; mi++)
#pragma unroll
                for (int ni = 0; ni < 4; ni++)
                    mma16816(c[mi][ni], a[cur][mi], b[cur][ni]);
        }
    };

    // prologue: two stages in flight
    issue(0, 0);
    cp_commit();
    issue(1, 1);
    cp_commit();

    int st = 0;
    for (int tt = 0; tt < TT; tt++) {
        if (tt + 1 < TT) cp_wait<1>(); else cp_wait<0>();
        __syncthreads();           // data visible + prev compute done
        if (tt + 2 < TT) {
            const int st2 = (st + 2 >= 3) ? st - 1 : st + 2;
            issue(tt + 2, st2);
            cp_commit();
        }
        compute(st);
        st = (st + 1 == 3) ? 0 : st + 1;
    }
    __syncthreads();

    // ---------------- epilogue via SMEM stage [128][132] fp32 --------------
    float* sEp = (float*)smem;
#pragma unroll
    for (int mi = 0; mi < 4; mi++)
#pragma unroll
        for (int ni = 0; ni < 4; ni++) {
            const int tm = wm + mi * 16 + (lane >> 2);
            const int tn = wn + ni * 8 + ((lane & 3) << 1);
            *(float2*)&sEp[tm * 132 + tn] =
                make_float2(c[mi][ni][0], c[mi][ni][1]);
            *(float2*)&sEp[(tm + 8) * 132 + tn] =
                make_float2(c[mi][ni][2], c[mi][ni][3]);
        }
    __syncthreads();

    if (EPI >= 2) {
        const int r = tid >> 1, ch = (tid & 1) << 6;
        const float* se = &sEp[r * 132 + ch];
        float* dst = outF + (size_t)(m0 + r) * Nstride + n0 + ch;
#pragma unroll
        for (int j = 0; j < 64; j += 4)
            *(float4*)(dst + j) =
                make_float4(se[j] * alpha, se[j + 1] * alpha,
                            se[j + 2] * alpha, se[j + 3] * alpha);
    } else if (EPI == 0) {
        const int r = tid >> 1, ch = (tid & 1) << 6;
        const float* se = &sEp[r * 132 + ch];
        const int nc = n0 + ch;
        const size_t ob = (size_t)(m0 + r) * Nstride + nc;
        uint32_t hh[32], ll[32];
#pragma unroll
        for (int j = 0; j < 32; j++)
            split_pack2(se[2 * j] + bias[nc + 2 * j],
                        se[2 * j + 1] + bias[nc + 2 * j + 1], hh[j], ll[j]);
#pragma unroll
        for (int j = 0; j < 8; j++) {
            *(uint4*)(outH + ob + j * 8) = make_uint4(
                hh[4 * j], hh[4 * j + 1], hh[4 * j + 2], hh[4 * j + 3]);
            *(uint4*)(outL + ob + j * 8) = make_uint4(
                ll[4 * j], ll[4 * j + 1], ll[4 * j + 2], ll[4 * j + 3]);
        }
    } else {  // EPI == 1: transposed split store  out[h][s]
        const int col = tid & 127;
        const int rh = (tid >> 7) << 6;   // 0 or 64
        const int h = n0 + col;
        const float bv = bias[h];
        uint32_t hh[32], ll[32];
#pragma unroll
        for (int j = 0; j < 32; j++)
            split_pack2(sEp[(rh + 2 * j) * 132 + col] + bv,
                        sEp[(rh + 2 * j + 1) * 132 + col] + bv, hh[j], ll[j]);
        const size_t ob = (size_t)h * SQ + m0 + rh;
#pragma unroll
        for (int j = 0; j < 8; j++) {
            *(uint4*)(outH + ob + j * 8) = make_uint4(
                hh[4 * j], hh[4 * j + 1], hh[4 * j + 2], hh[4 * j + 3]);
            *(uint4*)(outL + ob + j * 8) = make_uint4(
                ll[4 * j], ll[4 * j + 1], ll[4 * j + 2], ll[4 * j + 3]);
        }
    }
}

// ------------------------------- kernels -----------------------------------

__global__ void __launch_bounds__(256) conv_in(const float4* __restrict__ q,
                                               const float4* __restrict__ k,
                                               const float4* __restrict__ v) {
    const int i = blockIdx.x * 256 + threadIdx.x;
    float4 a = q[i], b = k[i], c = v[i];
    uint32_t h0, l0, h1, l1;
    split_pack2(a.x, a.y, h0, l0);
    split_pack2(a.z, a.w, h1, l1);
    ((uint2*)g_qh)[i] = make_uint2(h0, h1);
    ((uint2*)g_ql)[i] = make_uint2(l0, l1);
    split_pack2(b.x, b.y, h0, l0);
    split_pack2(b.z, b.w, h1, l1);
    ((uint2*)g_kh)[i] = make_uint2(h0, h1);
    ((uint2*)g_kl)[i] = make_uint2(l0, l1);
    split_pack2(c.x, c.y, h0, l0);
    split_pack2(c.z, c.w, h1, l1);
    ((uint2*)g_vh)[i] = make_uint2(h0, h1);
    ((uint2*)g_vl)[i] = make_uint2(l0, l1);
}

__global__ void __launch_bounds__(256) conv_w(const float* __restrict__ Wq,
                                              const float* __restrict__ Wk,
                                              const float* __restrict__ Wv) {
    __shared__ float t[32][33];
    const float* W = (blockIdx.z == 0) ? Wq : (blockIdx.z == 1) ? Wk : Wv;
    bf16* th = (blockIdx.z == 0) ? g_wqh : (blockIdx.z == 1) ? g_wkh : g_wvh;
    bf16* tl = (blockIdx.z == 0) ? g_wql : (blockIdx.z == 1) ? g_wkl : g_wvl;
    const int h0 = blockIdx.x * 32, d0 = blockIdx.y * 32;
    const int tx = threadIdx.x, ty = threadIdx.y;
#pragma unroll
    for (int r = 0; r < 32; r += 8)
        t[ty + r][tx] = W[(size_t)(d0 + ty + r) * HD + h0 + tx];
    __syncthreads();
#pragma unroll
    for (int r = 0; r < 32; r += 8) {
        const float v = t[tx][ty + r];
        const bf16 h = __float2bfloat16_rn(v);
        const bf16 l = __float2bfloat16_rn(v - __bfloat162float(h));
        const size_t o = (size_t)(h0 + ty + r) * DI + d0 + tx;
        th[o] = h;
        tl[o] = l;
    }
}

__global__ void __launch_bounds__(256, 2) k_proj_q(const float* __restrict__ b) {
    gemm_body<0>(g_qh, g_ql, g_wqh, g_wql, b, nullptr, g_Qh, g_Ql, DI, HD, 1.f);
}
__global__ void __launch_bounds__(256, 2) k_proj_k(const float* __restrict__ b) {
    gemm_body<0>(g_kh, g_kl, g_wkh, g_wkl, b, nullptr, g_Kh, g_Kl, DI, HD, 1.f);
}
__global__ void __launch_bounds__(256, 2) k_proj_v(const float* __restrict__ b) {
    gemm_body<1>(g_vh, g_vl, g_wvh, g_wvl, b, nullptr, g_Vth, g_Vtl, DI, SQ, 1.f);
}
__global__ void __launch_bounds__(256, 2) k_scores() {
    gemm_body<2>(g_Qh, g_Ql, g_Kh, g_Kl, nullptr, g_S, nullptr, nullptr, HD, SQ,
                 0.03125f);
}
__global__ void __launch_bounds__(256, 2) k_ctx(float* __restrict__ out) {
    gemm_body<3>(g_Ph, g_Pl, g_Vth, g_Vtl, nullptr, out, nullptr, nullptr, SQ,
                 HD, 1.f);
}

union F4 { float4 v; float f[4]; };

__global__ void __launch_bounds__(256) softmax_kernel() {
    const int row = blockIdx.x;
    const float* p = g_S + (size_t)row * SQ;
    const int tid = threadIdx.x;

    F4 v[4];
#pragma unroll
    for (int i = 0; i < 4; i++)
        v[i].v = *(const float4*)(p + tid * 4 + i * 1024);

    __shared__ float red[8];
    float m = -1e30f;
#pragma unroll
    for (int i = 0; i < 4; i++)
#pragma unroll
        for (int j = 0; j < 4; j++) m = fmaxf(m, v[i].f[j]);
#pragma unroll
    for (int o = 16; o > 0; o >>= 1)
        m = fmaxf(m, __shfl_xor_sync(0xffffffffu, m, o));
    if ((tid & 31) == 0) red[tid >> 5] = m;
    __syncthreads();
    float bm = red[0];
#pragma unroll
    for (int w = 1; w < 8; w++) bm = fmaxf(bm, red[w]);

    float s = 0.0f;
#pragma unroll
    for (int i = 0; i < 4; i++)
#pragma unroll
        for (int j = 0; j < 4; j++) {
            const float e = __expf(v[i].f[j] - bm);
            v[i].f[j] = e;
            s += e;
        }
#pragma unroll
    for (int o = 16; o > 0; o >>= 1) s += __shfl_xor_sync(0xffffffffu, s, o);
    __syncthreads();
    if ((tid & 31) == 0) red[tid >> 5] = s;
    __syncthreads();
    float bs = 0.0f;
#pragma unroll
    for (int w = 0; w < 8; w++) bs += red[w];
    const float inv = 1.0f / bs;

    const size_t base = (size_t)row * SQ;
#pragma unroll
    for (int i = 0; i < 4; i++) {
        uint32_t h0, l0, h1, l1;
        split_pack2(v[i].f[0] * inv, v[i].f[1] * inv, h0, l0);
        split_pack2(v[i].f[2] * inv, v[i].f[3] * inv, h1, l1);
        const size_t idx = base + tid * 4 + i * 1024;
        *(uint2*)(g_Ph + idx) = make_uint2(h0, h1);
        *(uint2*)(g_Pl + idx) = make_uint2(l0, l1);
    }
}

// ------------------------------ launcher -----------------------------------

extern "C" void kernel_launch(void* const* d_in, const int* in_sizes, int n_in,
                              void* d_out, int out_size) {
    const float* q = (const float*)d_in[0];
    const float* k = (const float*)d_in[1];
    const float* v = (const float*)d_in[2];
    const float* Wq = (const float*)d_in[3];
    const float* bq = (const float*)d_in[4];
    const float* Wk = (const float*)d_in[5];
    const float* bk = (const float*)d_in[6];
    const float* Wv = (const float*)d_in[7];
    const float* bv = (const float*)d_in[8];

    cudaFuncSetAttribute(k_proj_q, cudaFuncAttributeMaxDynamicSharedMemorySize,
                         SMEM_DYN);
    cudaFuncSetAttribute(k_proj_k, cudaFuncAttributeMaxDynamicSharedMemorySize,
                         SMEM_DYN);
    cudaFuncSetAttribute(k_proj_v, cudaFuncAttributeMaxDynamicSharedMemorySize,
                         SMEM_DYN);
    cudaFuncSetAttribute(k_scores, cudaFuncAttributeMaxDynamicSharedMemorySize,
                         SMEM_DYN);
    cudaFuncSetAttribute(k_ctx, cudaFuncAttributeMaxDynamicSharedMemorySize,
                         SMEM_DYN);

    conv_in<<<(SQ * DI / 4) / 256, 256>>>((const float4*)q, (const float4*)k,
                                          (const float4*)v);
    conv_w<<<dim3(HD / 32, DI / 32, 3), dim3(32, 8)>>>(Wq, Wk, Wv);

    k_proj_q<<<dim3(HD / 128, SQ / 128), 256, SMEM_DYN>>>(bq);
    k_proj_k<<<dim3(HD / 128, SQ / 128), 256, SMEM_DYN>>>(bk);
    k_proj_v<<<dim3(HD / 128, SQ / 128), 256, SMEM_DYN>>>(bv);

    k_scores<<<dim3(SQ / 128, SQ / 128), 256, SMEM_DYN>>>();
    softmax_kernel<<<SQ, 256>>>();
    k_ctx<<<dim3(HD / 128, SQ / 128), 256, SMEM_DYN>>>((float*)d_out);
}

// round 12
// speedup vs baseline: 1.0411x; 1.0411x over previous
#include <cuda_runtime.h>
#include <cuda_bf16.h>
#include <cstdint>
#include <cstddef>

#define SQ 4096
#define DI 1024
#define HD 1024

using bf16 = __nv_bfloat16;

// ---------------- device scratch (allocation-free rule) --------------------
__device__ __align__(16) bf16 g_qh[SQ * DI], g_ql[SQ * DI];
__device__ __align__(16) bf16 g_kh[SQ * DI], g_kl[SQ * DI];
__device__ __align__(16) bf16 g_vh[SQ * DI], g_vl[SQ * DI];
__device__ __align__(16) bf16 g_wqh[DI * HD], g_wql[DI * HD];
__device__ __align__(16) bf16 g_wkh[DI * HD], g_wkl[DI * HD];
__device__ __align__(16) bf16 g_wvh[DI * HD], g_wvl[DI * HD];
__device__ __align__(16) bf16 g_Qh[SQ * HD], g_Ql[SQ * HD];
__device__ __align__(16) bf16 g_Kh[SQ * HD], g_Kl[SQ * HD];
__device__ __align__(16) bf16 g_Vth[HD * SQ], g_Vtl[HD * SQ];   // V transposed
__device__ __align__(16) float g_S[(size_t)SQ * SQ];
__device__ __align__(16) bf16 g_Ph[(size_t)SQ * SQ], g_Pl[(size_t)SQ * SQ];

// ---------------- helpers ---------------------------------------------------
__device__ __forceinline__ uint32_t smem_u32(const void* p) {
    uint32_t a;
    asm("{ .reg .u64 t; cvta.to.shared.u64 t, %1; cvt.u32.u64 %0, t; }"
        : "=r"(a) : "l"(p));
    return a;
}

__device__ __forceinline__ void cp16(uint32_t dst, const void* src) {
    asm volatile("cp.async.cg.shared.global [%0], [%1], 16;"
                 :: "r"(dst), "l"(src));
}
__device__ __forceinline__ void cp_commit() {
    asm volatile("cp.async.commit_group;");
}
template <int N>
__device__ __forceinline__ void cp_wait() {
    asm volatile("cp.async.wait_group %0;" :: "n"(N));
}

__device__ __forceinline__ void ldsm4(uint32_t& r0, uint32_t& r1, uint32_t& r2,
                                      uint32_t& r3, uint32_t addr) {
    asm volatile(
        "ldmatrix.sync.aligned.m8n8.x4.shared.b16 {%0,%1,%2,%3}, [%4];"
        : "=r"(r0), "=r"(r1), "=r"(r2), "=r"(r3) : "r"(addr));
}

__device__ __forceinline__ void mma16816(float* c, const uint32_t* a,
                                         const uint32_t* b) {
    asm volatile(
        "mma.sync.aligned.m16n8k16.row.col.f32.bf16.bf16.f32 "
        "{%0,%1,%2,%3}, {%4,%5,%6,%7}, {%8,%9}, {%0,%1,%2,%3};"
        : "+f"(c[0]), "+f"(c[1]), "+f"(c[2]), "+f"(c[3])
        : "r"(a[0]), "r"(a[1]), "r"(a[2]), "r"(a[3]), "r"(b[0]), "r"(b[1]));
}

__device__ __forceinline__ void split_pack2(float a, float b, uint32_t& h,
                                            uint32_t& l) {
    bf16 ha = __float2bfloat16_rn(a);
    bf16 hb = __float2bfloat16_rn(b);
    bf16 la = __float2bfloat16_rn(a - __bfloat162float(ha));
    bf16 lb = __float2bfloat16_rn(b - __bfloat162float(hb));
    h = ((uint32_t)__bfloat16_as_ushort(hb) << 16) | __bfloat16_as_ushort(ha);
    l = ((uint32_t)__bfloat16_as_ushort(lb) << 16) | __bfloat16_as_ushort(la);
}

// ---------------------------------------------------------------------------
// D[128x128] = (Ah+Al)(Bh+Bl)^T minus lo*lo  (3 MMA terms per fragment set)
// NEW (R12): load Ah, Al, Bh, Bl tiles ONCE per k-step; issue all 3 MMA
// combos from the same fragments  => 33% less SMEM/LDSM + GMEM traffic.
// BK=32, XOR-16B swizzled tiles (no pitch padding), 3-stage cp.async ring,
// one __syncthreads per stage, __launch_bounds__(256,2): 2 CTAs/SM.
// EPI: 0 = bias + hi/lo split, row-major   1 = bias + split, transposed [h][s]
//      2 = fp32 * alpha                    3 = fp32
// ---------------------------------------------------------------------------
static constexpr int TILEB = 128 * 32 * 2;        // 8192 B per operand tile
static constexpr int STAGE = 4 * TILEB;           // Ah,Al,Bh,Bl = 32768 B
static constexpr int SMEM_DYN = 3 * STAGE;        // 98304 B

template <int EPI>
__device__ __forceinline__ void gemm_body(
    const bf16* __restrict__ Ah, const bf16* __restrict__ Al,
    const bf16* __restrict__ Bh, const bf16* __restrict__ Bl,
    const float* __restrict__ bias, float* __restrict__ outF,
    bf16* __restrict__ outH, bf16* __restrict__ outL, int Ktot, int Nstride,
    float alpha) {
    extern __shared__ char smem[];
    const uint32_t sBase = smem_u32(smem);

    const int tid = threadIdx.x;
    const int lane = tid & 31, wid = tid >> 5;
    const int wm = (wid >> 2) << 6;   // 0,64
    const int wn = (wid & 3) << 5;    // 0,32,64,96
    const int m0 = blockIdx.y << 7, n0 = blockIdx.x << 7;

    float c[4][4][4];
#pragma unroll
    for (int i = 0; i < 4; i++)
#pragma unroll
        for (int j = 0; j < 4; j++)
#pragma unroll
            for (int q = 0; q < 4; q++) c[i][j][q] = 0.0f;

    const int T = Ktot >> 5;                 // BK = 32

    // ---- cp.async: thread -> (row, 2 chunks of 16B), XOR swizzle ----------
    const int crow = tid >> 1;               // 0..127
    const int cc2 = (tid & 1) << 1;          // chunk 0 or 2
    const uint32_t cxor = (uint32_t)((crow >> 1) & 3);

    auto issue = [&](int kt, int st) {
        const uint32_t stg = sBase + st * STAGE;
        const bf16* srcs[4] = {
            Ah + (size_t)(m0 + crow) * Ktot + (kt << 5) + (cc2 << 3),
            Al + (size_t)(m0 + crow) * Ktot + (kt << 5) + (cc2 << 3),
            Bh + (size_t)(n0 + crow) * Ktot + (kt << 5) + (cc2 << 3),
            Bl + (size_t)(n0 + crow) * Ktot + (kt << 5) + (cc2 << 3)};
#pragma unroll
        for (int s = 0; s < 4; s++) {
            const uint32_t rb = stg + s * TILEB + (uint32_t)(crow << 6);
            cp16(rb + (((uint32_t)cc2 ^ cxor) << 4), srcs[s]);
            cp16(rb + (((uint32_t)(cc2 + 1) ^ cxor) << 4), srcs[s] + 8);
        }
    };

    // ---- ldmatrix lane addressing ------------------------------------------
    const int arow = wm + (lane & 15);
    const uint32_t aRowOff = (uint32_t)(arow << 6);
    const uint32_t axor = (uint32_t)((arow >> 1) & 3);
    const uint32_t ahi = (uint32_t)(lane >> 4);
    const int brow = wn + (lane & 7) + ((lane >> 4) << 3);
    const uint32_t bRowOff = (uint32_t)(brow << 6);
    const uint32_t bxor = (uint32_t)((brow >> 1) & 3);
    const uint32_t bbit = (uint32_t)((lane >> 3) & 1);

    auto compute = [&](int st) {
        const uint32_t stg = sBase + st * STAGE;
#pragma unroll
        for (int kk = 0; kk < 2; kk++) {
            const uint32_t aco = ((((uint32_t)(kk << 1)) + ahi) ^ axor) << 4;
            const uint32_t bco = ((((uint32_t)(kk << 1)) + bbit) ^ bxor) << 4;
            uint32_t ah[4][4], al[4][4], bh[4][2], bl[4][2];
            // Ah + Bh + Bl fragments
#pragma unroll
            for (int mi = 0; mi < 4; mi++)
                ldsm4(ah[mi][0], ah[mi][1], ah[mi][2], ah[mi][3],
                      stg + aRowOff + (uint32_t)(mi << 10) + aco);
#pragma unroll
            for (int j = 0; j < 2; j++) {
                uint32_t r0, r1, r2, r3;
                ldsm4(r0, r1, r2, r3, stg + 2u * TILEB + bRowOff +
                                          (uint32_t)(j << 10) + bco);
                bh[2 * j][0] = r0; bh[2 * j][1] = r1;
                bh[2 * j + 1][0] = r2; bh[2 * j + 1][1] = r3;
            }
#pragma unroll
            for (int j = 0; j < 2; j++) {
                uint32_t r0, r1, r2, r3;
                ldsm4(r0, r1, r2, r3, stg + 3u * TILEB + bRowOff +
                                          (uint32_t)(j << 10) + bco);
                bl[2 * j][0] = r0; bl[2 * j][1] = r1;
                bl[2 * j + 1][0] = r2; bl[2 * j + 1][1] = r3;
            }
            // Ah*Bh (covers Bl ldsm latency)
#pragma unroll
            for (int mi = 0; mi < 4; mi++)
#pragma unroll
                for (int ni = 0; ni < 4; ni++)
                    mma16816(c[mi][ni], ah[mi], bh[ni]);
            // Al fragments
#pragma unroll
            for (int mi = 0; mi < 4; mi++)
                ldsm4(al[mi][0], al[mi][1], al[mi][2], al[mi][3],
                      stg + TILEB + aRowOff + (uint32_t)(mi << 10) + aco);
            // Ah*Bl (covers Al ldsm latency)
#pragma unroll
            for (int mi = 0; mi < 4; mi++)
#pragma unroll
                for (int ni = 0; ni < 4; ni++)
                    mma16816(c[mi][ni], ah[mi], bl[ni]);
            // Al*Bh
#pragma unroll
            for (int mi = 0; mi < 4; mi++)
#pragma unroll
                for (int ni = 0; ni < 4; ni++)
                    mma16816(c[mi][ni], al[mi], bh[ni]);
        }
    };

    // prologue: two stages in flight
    issue(0, 0);
    cp_commit();
    issue(1, 1);
    cp_commit();

    int st = 0;
    for (int t = 0; t < T; t++) {
        if (t + 1 < T) cp_wait<1>(); else cp_wait<0>();
        __syncthreads();
        if (t + 2 < T) {
            const int st2 = (st + 2 >= 3) ? st - 1 : st + 2;
            issue(t + 2, st2);
            cp_commit();
        }
        compute(st);
        st = (st + 1 == 3) ? 0 : st + 1;
    }
    __syncthreads();

    // ---------------- epilogue via SMEM stage [128][132] fp32 --------------
    float* sEp = (float*)smem;
#pragma unroll
    for (int mi = 0; mi < 4; mi++)
#pragma unroll
        for (int ni = 0; ni < 4; ni++) {
            const int tm = wm + mi * 16 + (lane >> 2);
            const int tn = wn + ni * 8 + ((lane & 3) << 1);
            *(float2*)&sEp[tm * 132 + tn] =
                make_float2(c[mi][ni][0], c[mi][ni][1]);
            *(float2*)&sEp[(tm + 8) * 132 + tn] =
                make_float2(c[mi][ni][2], c[mi][ni][3]);
        }
    __syncthreads();

    if (EPI >= 2) {
        const int r = tid >> 1, ch = (tid & 1) << 6;
        const float* se = &sEp[r * 132 + ch];
        float* dst = outF + (size_t)(m0 + r) * Nstride + n0 + ch;
#pragma unroll
        for (int j = 0; j < 64; j += 4)
            *(float4*)(dst + j) =
                make_float4(se[j] * alpha, se[j + 1] * alpha,
                            se[j + 2] * alpha, se[j + 3] * alpha);
    } else if (EPI == 0) {
        const int r = tid >> 1, ch = (tid & 1) << 6;
        const float* se = &sEp[r * 132 + ch];
        const int nc = n0 + ch;
        const size_t ob = (size_t)(m0 + r) * Nstride + nc;
        uint32_t hh[32], ll[32];
#pragma unroll
        for (int j = 0; j < 32; j++)
            split_pack2(se[2 * j] + bias[nc + 2 * j],
                        se[2 * j + 1] + bias[nc + 2 * j + 1], hh[j], ll[j]);
#pragma unroll
        for (int j = 0; j < 8; j++) {
            *(uint4*)(outH + ob + j * 8) = make_uint4(
                hh[4 * j], hh[4 * j + 1], hh[4 * j + 2], hh[4 * j + 3]);
            *(uint4*)(outL + ob + j * 8) = make_uint4(
                ll[4 * j], ll[4 * j + 1], ll[4 * j + 2], ll[4 * j + 3]);
        }
    } else {  // EPI == 1: transposed split store  out[h][s]
        const int col = tid & 127;
        const int rh = (tid >> 7) << 6;   // 0 or 64
        const int h = n0 + col;
        const float bv = bias[h];
        uint32_t hh[32], ll[32];
#pragma unroll
        for (int j = 0; j < 32; j++)
            split_pack2(sEp[(rh + 2 * j) * 132 + col] + bv,
                        sEp[(rh + 2 * j + 1) * 132 + col] + bv, hh[j], ll[j]);
        const size_t ob = (size_t)h * SQ + m0 + rh;
#pragma unroll
        for (int j = 0; j < 8; j++) {
            *(uint4*)(outH + ob + j * 8) = make_uint4(
                hh[4 * j], hh[4 * j + 1], hh[4 * j + 2], hh[4 * j + 3]);
            *(uint4*)(outL + ob + j * 8) = make_uint4(
                ll[4 * j], ll[4 * j + 1], ll[4 * j + 2], ll[4 * j + 3]);
        }
    }
}

// ------------------------------- kernels -----------------------------------

__global__ void __launch_bounds__(256) conv_in(const float4* __restrict__ q,
                                               const float4* __restrict__ k,
                                               const float4* __restrict__ v) {
    const int i = blockIdx.x * 256 + threadIdx.x;
    float4 a = q[i], b = k[i], c = v[i];
    uint32_t h0, l0, h1, l1;
    split_pack2(a.x, a.y, h0, l0);
    split_pack2(a.z, a.w, h1, l1);
    ((uint2*)g_qh)[i] = make_uint2(h0, h1);
    ((uint2*)g_ql)[i] = make_uint2(l0, l1);
    split_pack2(b.x, b.y, h0, l0);
    split_pack2(b.z, b.w, h1, l1);
    ((uint2*)g_kh)[i] = make_uint2(h0, h1);
    ((uint2*)g_kl)[i] = make_uint2(l0, l1);
    split_pack2(c.x, c.y, h0, l0);
    split_pack2(c.z, c.w, h1, l1);
    ((uint2*)g_vh)[i] = make_uint2(h0, h1);
    ((uint2*)g_vl)[i] = make_uint2(l0, l1);
}

__global__ void __launch_bounds__(256) conv_w(const float* __restrict__ Wq,
                                              const float* __restrict__ Wk,
                                              const float* __restrict__ Wv) {
    __shared__ float t[32][33];
    const float* W = (blockIdx.z == 0) ? Wq : (blockIdx.z == 1) ? Wk : Wv;
    bf16* th = (blockIdx.z == 0) ? g_wqh : (blockIdx.z == 1) ? g_wkh : g_wvh;
    bf16* tl = (blockIdx.z == 0) ? g_wql : (blockIdx.z == 1) ? g_wkl : g_wvl;
    const int h0 = blockIdx.x * 32, d0 = blockIdx.y * 32;
    const int tx = threadIdx.x, ty = threadIdx.y;
#pragma unroll
    for (int r = 0; r < 32; r += 8)
        t[ty + r][tx] = W[(size_t)(d0 + ty + r) * HD + h0 + tx];
    __syncthreads();
#pragma unroll
    for (int r = 0; r < 32; r += 8) {
        const float v = t[tx][ty + r];
        const bf16 h = __float2bfloat16_rn(v);
        const bf16 l = __float2bfloat16_rn(v - __bfloat162float(h));
        const size_t o = (size_t)(h0 + ty + r) * DI + d0 + tx;
        th[o] = h;
        tl[o] = l;
    }
}

__global__ void __launch_bounds__(256, 2) k_proj_q(const float* __restrict__ b) {
    gemm_body<0>(g_qh, g_ql, g_wqh, g_wql, b, nullptr, g_Qh, g_Ql, DI, HD, 1.f);
}
__global__ void __launch_bounds__(256, 2) k_proj_k(const float* __restrict__ b) {
    gemm_body<0>(g_kh, g_kl, g_wkh, g_wkl, b, nullptr, g_Kh, g_Kl, DI, HD, 1.f);
}
__global__ void __launch_bounds__(256, 2) k_proj_v(const float* __restrict__ b) {
    gemm_body<1>(g_vh, g_vl, g_wvh, g_wvl, b, nullptr, g_Vth, g_Vtl, DI, SQ, 1.f);
}
__global__ void __launch_bounds__(256, 2) k_scores() {
    gemm_body<2>(g_Qh, g_Ql, g_Kh, g_Kl, nullptr, g_S, nullptr, nullptr, HD, SQ,
                 0.03125f);
}
__global__ void __launch_bounds__(256, 2) k_ctx(float* __restrict__ out) {
    gemm_body<3>(g_Ph, g_Pl, g_Vth, g_Vtl, nullptr, out, nullptr, nullptr, SQ,
                 HD, 1.f);
}

union F4 { float4 v; float f[4]; };

__global__ void __launch_bounds__(256) softmax_kernel() {
    const int row = blockIdx.x;
    const float* p = g_S + (size_t)row * SQ;
    const int tid = threadIdx.x;

    F4 v[4];
#pragma unroll
    for (int i = 0; i < 4; i++)
        v[i].v = *(const float4*)(p + tid * 4 + i * 1024);

    __shared__ float red[8];
    float m = -1e30f;
#pragma unroll
    for (int i = 0; i < 4; i++)
#pragma unroll
        for (int j = 0; j < 4; j++) m = fmaxf(m, v[i].f[j]);
#pragma unroll
    for (int o = 16; o > 0; o >>= 1)
        m = fmaxf(m, __shfl_xor_sync(0xffffffffu, m, o));
    if ((tid & 31) == 0) red[tid >> 5] = m;
    __syncthreads();
    float bm = red[0];
#pragma unroll
    for (int w = 1; w < 8; w++) bm = fmaxf(bm, red[w]);

    float s = 0.0f;
#pragma unroll
    for (int i = 0; i < 4; i++)
#pragma unroll
        for (int j = 0; j < 4; j++) {
            const float e = __expf(v[i].f[j] - bm);
            v[i].f[j] = e;
            s += e;
        }
#pragma unroll
    for (int o = 16; o > 0; o >>= 1) s += __shfl_xor_sync(0xffffffffu, s, o);
    __syncthreads();
    if ((tid & 31) == 0) red[tid >> 5] = s;
    __syncthreads();
    float bs = 0.0f;
#pragma unroll
    for (int w = 0; w < 8; w++) bs += red[w];
    const float inv = 1.0f / bs;

    const size_t base = (size_t)row * SQ;
#pragma unroll
    for (int i = 0; i < 4; i++) {
        uint32_t h0, l0, h1, l1;
        split_pack2(v[i].f[0] * inv, v[i].f[1] * inv, h0, l0);
        split_pack2(v[i].f[2] * inv, v[i].f[3] * inv, h1, l1);
        const size_t idx = base + tid * 4 + i * 1024;
        *(uint2*)(g_Ph + idx) = make_uint2(h0, h1);
        *(uint2*)(g_Pl + idx) = make_uint2(l0, l1);
    }
}

// ------------------------------ launcher -----------------------------------

extern "C" void kernel_launch(void* const* d_in, const int* in_sizes, int n_in,
                              void* d_out, int out_size) {
    const float* q = (const float*)d_in[0];
    const float* k = (const float*)d_in[1];
    const float* v = (const float*)d_in[2];
    const float* Wq = (const float*)d_in[3];
    const float* bq = (const float*)d_in[4];
    const float* Wk = (const float*)d_in[5];
    const float* bk = (const float*)d_in[6];
    const float* Wv = (const float*)d_in[7];
    const float* bv = (const float*)d_in[8];

    cudaFuncSetAttribute(k_proj_q, cudaFuncAttributeMaxDynamicSharedMemorySize,
                         SMEM_DYN);
    cudaFuncSetAttribute(k_proj_k, cudaFuncAttributeMaxDynamicSharedMemorySize,
                         SMEM_DYN);
    cudaFuncSetAttribute(k_proj_v, cudaFuncAttributeMaxDynamicSharedMemorySize,
                         SMEM_DYN);
    cudaFuncSetAttribute(k_scores, cudaFuncAttributeMaxDynamicSharedMemorySize,
                         SMEM_DYN);
    cudaFuncSetAttribute(k_ctx, cudaFuncAttributeMaxDynamicSharedMemorySize,
                         SMEM_DYN);

    conv_in<<<(SQ * DI / 4) / 256, 256>>>((const float4*)q, (const float4*)k,
                                          (const float4*)v);
    conv_w<<<dim3(HD / 32, DI / 32, 3), dim3(32, 8)>>>(Wq, Wk, Wv);

    k_proj_q<<<dim3(HD / 128, SQ / 128), 256, SMEM_DYN>>>(bq);
    k_proj_k<<<dim3(HD / 128, SQ / 128), 256, SMEM_DYN>>>(bk);
    k_proj_v<<<dim3(HD / 128, SQ / 128), 256, SMEM_DYN>>>(bv);

    k_scores<<<dim3(SQ / 128, SQ / 128), 256, SMEM_DYN>>>();
    softmax_kernel<<<SQ, 256>>>();
    k_ctx<<<dim3(HD / 128, SQ / 128), 256, SMEM_DYN>>>((float*)d_out);
}

// round 13
// speedup vs baseline: 1.1208x; 1.0765x over previous
#include <cuda_runtime.h>
#include <cuda_bf16.h>
#include <cstdint>
#include <cstddef>

#define SQ 4096
#define DI 1024
#define HD 1024

using bf16 = __nv_bfloat16;

// ---------------- device scratch (allocation-free rule) --------------------
__device__ __align__(16) bf16 g_qh[SQ * DI], g_ql[SQ * DI];
__device__ __align__(16) bf16 g_kh[SQ * DI], g_kl[SQ * DI];
__device__ __align__(16) bf16 g_vh[SQ * DI], g_vl[SQ * DI];
__device__ __align__(16) bf16 g_wqh[DI * HD], g_wql[DI * HD];
__device__ __align__(16) bf16 g_wkh[DI * HD], g_wkl[DI * HD];
__device__ __align__(16) bf16 g_wvh[DI * HD], g_wvl[DI * HD];
__device__ __align__(16) bf16 g_Qh[SQ * HD], g_Ql[SQ * HD];
__device__ __align__(16) bf16 g_Kh[SQ * HD], g_Kl[SQ * HD];
__device__ __align__(16) bf16 g_Vth[HD * SQ], g_Vtl[HD * SQ];   // V transposed
__device__ __align__(16) float g_S[(size_t)SQ * SQ];
__device__ __align__(16) bf16 g_Ph[(size_t)SQ * SQ], g_Pl[(size_t)SQ * SQ];

// ---------------- helpers ---------------------------------------------------
__device__ __forceinline__ uint32_t smem_u32(const void* p) {
    uint32_t a;
    asm("{ .reg .u64 t; cvta.to.shared.u64 t, %1; cvt.u32.u64 %0, t; }"
        : "=r"(a) : "l"(p));
    return a;
}

__device__ __forceinline__ void cp16(uint32_t dst, const void* src) {
    asm volatile("cp.async.cg.shared.global [%0], [%1], 16;"
                 :: "r"(dst), "l"(src));
}
__device__ __forceinline__ void cp_commit() {
    asm volatile("cp.async.commit_group;");
}
template <int N>
__device__ __forceinline__ void cp_wait() {
    asm volatile("cp.async.wait_group %0;" :: "n"(N));
}

__device__ __forceinline__ void ldsm4(uint32_t& r0, uint32_t& r1, uint32_t& r2,
                                      uint32_t& r3, uint32_t addr) {
    asm volatile(
        "ldmatrix.sync.aligned.m8n8.x4.shared.b16 {%0,%1,%2,%3}, [%4];"
        : "=r"(r0), "=r"(r1), "=r"(r2), "=r"(r3) : "r"(addr));
}

__device__ __forceinline__ void mma16816(float* c, const uint32_t* a,
                                         const uint32_t* b) {
    asm volatile(
        "mma.sync.aligned.m16n8k16.row.col.f32.bf16.bf16.f32 "
        "{%0,%1,%2,%3}, {%4,%5,%6,%7}, {%8,%9}, {%0,%1,%2,%3};"
        : "+f"(c[0]), "+f"(c[1]), "+f"(c[2]), "+f"(c[3])
        : "r"(a[0]), "r"(a[1]), "r"(a[2]), "r"(a[3]), "r"(b[0]), "r"(b[1]));
}

__device__ __forceinline__ void split_pack2(float a, float b, uint32_t& h,
                                            uint32_t& l) {
    bf16 ha = __float2bfloat16_rn(a);
    bf16 hb = __float2bfloat16_rn(b);
    bf16 la = __float2bfloat16_rn(a - __bfloat162float(ha));
    bf16 lb = __float2bfloat16_rn(b - __bfloat162float(hb));
    h = ((uint32_t)__bfloat16_as_ushort(hb) << 16) | __bfloat16_as_ushort(ha);
    l = ((uint32_t)__bfloat16_as_ushort(lb) << 16) | __bfloat16_as_ushort(la);
}

// ---------------------------------------------------------------------------
// D[128x128] = (Ah+Al)(Bh+Bl)^T minus lo*lo  (3 MMA terms per fragment set)
// R13: cp.async issue is interleaved BETWEEN MMA groups (de-burst LSU, MMAs
// start right after the barrier). BK=32, XOR-16B swizzle, 3-stage ring,
// one __syncthreads per stage, 2 CTAs/SM.
// epi: 0 = bias + hi/lo split row-major; 1 = bias + split transposed [h][s];
//      2 = fp32 * alpha; 3 = fp32.   (epi is runtime for the proj kernel,
//      compile-time-constant at the scores/ctx call sites.)
// ---------------------------------------------------------------------------
static constexpr int TILEB = 128 * 32 * 2;        // 8192 B per operand tile
static constexpr int STAGE = 4 * TILEB;           // Ah,Al,Bh,Bl = 32768 B
static constexpr int SMEM_DYN = 3 * STAGE;        // 98304 B

__device__ __forceinline__ void gemm_body(
    int epi, const bf16* __restrict__ Ah, const bf16* __restrict__ Al,
    const bf16* __restrict__ Bh, const bf16* __restrict__ Bl,
    const float* __restrict__ bias, float* __restrict__ outF,
    bf16* __restrict__ outH, bf16* __restrict__ outL, int Ktot, int Nstride,
    float alpha) {
    extern __shared__ char smem[];
    const uint32_t sBase = smem_u32(smem);

    const int tid = threadIdx.x;
    const int lane = tid & 31, wid = tid >> 5;
    const int wm = (wid >> 2) << 6;   // 0,64
    const int wn = (wid & 3) << 5;    // 0,32,64,96
    const int m0 = blockIdx.y << 7, n0 = blockIdx.x << 7;

    float c[4][4][4];
#pragma unroll
    for (int i = 0; i < 4; i++)
#pragma unroll
        for (int j = 0; j < 4; j++)
#pragma unroll
            for (int q = 0; q < 4; q++) c[i][j][q] = 0.0f;

    const int T = Ktot >> 5;                 // BK = 32

    // ---- cp.async: thread -> (row, 2 chunks of 16B), XOR swizzle ----------
    const int crow = tid >> 1;               // 0..127
    const int cc2 = (tid & 1) << 1;          // chunk 0 or 2
    const uint32_t cxor = (uint32_t)((crow >> 1) & 3);
    const uint32_t co0 = ((uint32_t)cc2 ^ cxor) << 4;
    const uint32_t co1 = ((uint32_t)(cc2 + 1) ^ cxor) << 4;

    // half 0 = Ah,Al tiles; half 1 = Bh,Bl tiles
    auto issueHalf = [&](int kt, int st, int half) {
        const bf16* s0;
        const bf16* s1;
        if (half == 0) {
            s0 = Ah + (size_t)(m0 + crow) * Ktot + (kt << 5) + (cc2 << 3);
            s1 = Al + (size_t)(m0 + crow) * Ktot + (kt << 5) + (cc2 << 3);
        } else {
            s0 = Bh + (size_t)(n0 + crow) * Ktot + (kt << 5) + (cc2 << 3);
            s1 = Bl + (size_t)(n0 + crow) * Ktot + (kt << 5) + (cc2 << 3);
        }
        const uint32_t rb = sBase + st * STAGE +
                            (half ? 2u * TILEB : 0u) + (uint32_t)(crow << 6);
        cp16(rb + co0, s0);
        cp16(rb + co1, s0 + 8);
        cp16(rb + TILEB + co0, s1);
        cp16(rb + TILEB + co1, s1 + 8);
    };

    // ---- ldmatrix lane addressing ------------------------------------------
    const int arow = wm + (lane & 15);
    const uint32_t aRowOff = (uint32_t)(arow << 6);
    const uint32_t axor = (uint32_t)((arow >> 1) & 3);
    const uint32_t ahi = (uint32_t)(lane >> 4);
    const int brow = wn + (lane & 7) + ((lane >> 4) << 3);
    const uint32_t bRowOff = (uint32_t)(brow << 6);
    const uint32_t bxor = (uint32_t)((brow >> 1) & 3);
    const uint32_t bbit = (uint32_t)((lane >> 3) & 1);

    auto compute = [&](int st, int kt2, int st2, bool doIss) {
        const uint32_t stg = sBase + st * STAGE;
#pragma unroll
        for (int kk = 0; kk < 2; kk++) {
            const uint32_t aco = ((((uint32_t)(kk << 1)) + ahi) ^ axor) << 4;
            const uint32_t bco = ((((uint32_t)(kk << 1)) + bbit) ^ bxor) << 4;
            uint32_t ah[4][4], al[4][4], bh[4][2], bl[4][2];
#pragma unroll
            for (int mi = 0; mi < 4; mi++)
                ldsm4(ah[mi][0], ah[mi][1], ah[mi][2], ah[mi][3],
                      stg + aRowOff + (uint32_t)(mi << 10) + aco);
#pragma unroll
            for (int j = 0; j < 2; j++) {
                uint32_t r0, r1, r2, r3;
                ldsm4(r0, r1, r2, r3, stg + 2u * TILEB + bRowOff +
                                          (uint32_t)(j << 10) + bco);
                bh[2 * j][0] = r0; bh[2 * j][1] = r1;
                bh[2 * j + 1][0] = r2; bh[2 * j + 1][1] = r3;
            }
#pragma unroll
            for (int j = 0; j < 2; j++) {
                uint32_t r0, r1, r2, r3;
                ldsm4(r0, r1, r2, r3, stg + 3u * TILEB + bRowOff +
                                          (uint32_t)(j << 10) + bco);
                bl[2 * j][0] = r0; bl[2 * j][1] = r1;
                bl[2 * j + 1][0] = r2; bl[2 * j + 1][1] = r3;
            }
            // Ah*Bh
#pragma unroll
            for (int mi = 0; mi < 4; mi++)
#pragma unroll
                for (int ni = 0; ni < 4; ni++)
                    mma16816(c[mi][ni], ah[mi], bh[ni]);
            // Al fragments
#pragma unroll
            for (int mi = 0; mi < 4; mi++)
                ldsm4(al[mi][0], al[mi][1], al[mi][2], al[mi][3],
                      stg + TILEB + aRowOff + (uint32_t)(mi << 10) + aco);
            if (kk == 0 && doIss) issueHalf(kt2, st2, 0);  // A copies under MMA
            // Ah*Bl
#pragma unroll
            for (int mi = 0; mi < 4; mi++)
#pragma unroll
                for (int ni = 0; ni < 4; ni++)
                    mma16816(c[mi][ni], ah[mi], bl[ni]);
            if (kk == 0 && doIss) issueHalf(kt2, st2, 1);  // B copies under MMA
            // Al*Bh
#pragma unroll
            for (int mi = 0; mi < 4; mi++)
#pragma unroll
                for (int ni = 0; ni < 4; ni++)
                    mma16816(c[mi][ni], al[mi], bh[ni]);
        }
    };

    // prologue: two stages in flight
    issueHalf(0, 0, 0);
    issueHalf(0, 0, 1);
    cp_commit();
    issueHalf(1, 1, 0);
    issueHalf(1, 1, 1);
    cp_commit();

    int st = 0;
    for (int t = 0; t < T; t++) {
        if (t + 1 < T) cp_wait<1>(); else cp_wait<0>();
        __syncthreads();
        const int st2 = (st + 2 >= 3) ? st - 1 : st + 2;
        compute(st, t + 2, st2, t + 2 < T);
        cp_commit();
        st = (st + 1 == 3) ? 0 : st + 1;
    }
    __syncthreads();

    // ---------------- epilogue via SMEM stage [128][132] fp32 --------------
    float* sEp = (float*)smem;
#pragma unroll
    for (int mi = 0; mi < 4; mi++)
#pragma unroll
        for (int ni = 0; ni < 4; ni++) {
            const int tm = wm + mi * 16 + (lane >> 2);
            const int tn = wn + ni * 8 + ((lane & 3) << 1);
            *(float2*)&sEp[tm * 132 + tn] =
                make_float2(c[mi][ni][0], c[mi][ni][1]);
            *(float2*)&sEp[(tm + 8) * 132 + tn] =
                make_float2(c[mi][ni][2], c[mi][ni][3]);
        }
    __syncthreads();

    if (epi >= 2) {
        const int r = tid >> 1, ch = (tid & 1) << 6;
        const float* se = &sEp[r * 132 + ch];
        float* dst = outF + (size_t)(m0 + r) * Nstride + n0 + ch;
#pragma unroll
        for (int j = 0; j < 64; j += 4)
            *(float4*)(dst + j) =
                make_float4(se[j] * alpha, se[j + 1] * alpha,
                            se[j + 2] * alpha, se[j + 3] * alpha);
    } else if (epi == 0) {
        const int r = tid >> 1, ch = (tid & 1) << 6;
        const float* se = &sEp[r * 132 + ch];
        const int nc = n0 + ch;
        const size_t ob = (size_t)(m0 + r) * Nstride + nc;
        uint32_t hh[32], ll[32];
#pragma unroll
        for (int j = 0; j < 32; j++)
            split_pack2(se[2 * j] + bias[nc + 2 * j],
                        se[2 * j + 1] + bias[nc + 2 * j + 1], hh[j], ll[j]);
#pragma unroll
        for (int j = 0; j < 8; j++) {
            *(uint4*)(outH + ob + j * 8) = make_uint4(
                hh[4 * j], hh[4 * j + 1], hh[4 * j + 2], hh[4 * j + 3]);
            *(uint4*)(outL + ob + j * 8) = make_uint4(
                ll[4 * j], ll[4 * j + 1], ll[4 * j + 2], ll[4 * j + 3]);
        }
    } else {  // epi == 1: transposed split store  out[h][s]
        const int col = tid & 127;
        const int rh = (tid >> 7) << 6;   // 0 or 64
        const int h = n0 + col;
        const float bv = bias[h];
        uint32_t hh[32], ll[32];
#pragma unroll
        for (int j = 0; j < 32; j++)
            split_pack2(sEp[(rh + 2 * j) * 132 + col] + bv,
                        sEp[(rh + 2 * j + 1) * 132 + col] + bv, hh[j], ll[j]);
        const size_t ob = (size_t)h * SQ + m0 + rh;
#pragma unroll
        for (int j = 0; j < 8; j++) {
            *(uint4*)(outH + ob + j * 8) = make_uint4(
                hh[4 * j], hh[4 * j + 1], hh[4 * j + 2], hh[4 * j + 3]);
            *(uint4*)(outL + ob + j * 8) = make_uint4(
                ll[4 * j], ll[4 * j + 1], ll[4 * j + 2], ll[4 * j + 3]);
        }
    }
}

// ------------------------------- kernels -----------------------------------

__global__ void __launch_bounds__(256) conv_in(const float4* __restrict__ q,
                                               const float4* __restrict__ k,
                                               const float4* __restrict__ v) {
    const int i = blockIdx.x * 256 + threadIdx.x;
    float4 a = q[i], b = k[i], c = v[i];
    uint32_t h0, l0, h1, l1;
    split_pack2(a.x, a.y, h0, l0);
    split_pack2(a.z, a.w, h1, l1);
    ((uint2*)g_qh)[i] = make_uint2(h0, h1);
    ((uint2*)g_ql)[i] = make_uint2(l0, l1);
    split_pack2(b.x, b.y, h0, l0);
    split_pack2(b.z, b.w, h1, l1);
    ((uint2*)g_kh)[i] = make_uint2(h0, h1);
    ((uint2*)g_kl)[i] = make_uint2(l0, l1);
    split_pack2(c.x, c.y, h0, l0);
    split_pack2(c.z, c.w, h1, l1);
    ((uint2*)g_vh)[i] = make_uint2(h0, h1);
    ((uint2*)g_vl)[i] = make_uint2(l0, l1);
}

__global__ void __launch_bounds__(256) conv_w(const float* __restrict__ Wq,
                                              const float* __restrict__ Wk,
                                              const float* __restrict__ Wv) {
    __shared__ float t[32][33];
    const float* W = (blockIdx.z == 0) ? Wq : (blockIdx.z == 1) ? Wk : Wv;
    bf16* th = (blockIdx.z == 0) ? g_wqh : (blockIdx.z == 1) ? g_wkh : g_wvh;
    bf16* tl = (blockIdx.z == 0) ? g_wql : (blockIdx.z == 1) ? g_wkl : g_wvl;
    const int h0 = blockIdx.x * 32, d0 = blockIdx.y * 32;
    const int tx = threadIdx.x, ty = threadIdx.y;
#pragma unroll
    for (int r = 0; r < 32; r += 8)
        t[ty + r][tx] = W[(size_t)(d0 + ty + r) * HD + h0 + tx];
    __syncthreads();
#pragma unroll
    for (int r = 0; r < 32; r += 8) {
        const float v = t[tx][ty + r];
        const bf16 h = __float2bfloat16_rn(v);
        const bf16 l = __float2bfloat16_rn(v - __bfloat162float(h));
        const size_t o = (size_t)(h0 + ty + r) * DI + d0 + tx;
        th[o] = h;
        tl[o] = l;
    }
}

// merged Q/K/V projection: grid.z selects the problem; one code body.
__global__ void __launch_bounds__(256, 2) k_proj_all(
    const float* __restrict__ bq, const float* __restrict__ bk,
    const float* __restrict__ bv) {
    const int z = blockIdx.z;
    const bf16* Ah = (z == 0) ? g_qh : (z == 1) ? g_kh : g_vh;
    const bf16* Al = (z == 0) ? g_ql : (z == 1) ? g_kl : g_vl;
    const bf16* Bh = (z == 0) ? g_wqh : (z == 1) ? g_wkh : g_wvh;
    const bf16* Bl = (z == 0) ? g_wql : (z == 1) ? g_wkl : g_wvl;
    const float* bias = (z == 0) ? bq : (z == 1) ? bk : bv;
    bf16* oh = (z == 0) ? g_Qh : (z == 1) ? g_Kh : g_Vth;
    bf16* ol = (z == 0) ? g_Ql : (z == 1) ? g_Kl : g_Vtl;
    const int epi = (z == 2) ? 1 : 0;
    const int nstr = (z == 2) ? SQ : HD;
    gemm_body(epi, Ah, Al, Bh, Bl, bias, nullptr, oh, ol, DI, nstr, 1.f);
}

__global__ void __launch_bounds__(256, 2) k_scores() {
    gemm_body(2, g_Qh, g_Ql, g_Kh, g_Kl, nullptr, g_S, nullptr, nullptr, HD,
              SQ, 0.03125f);
}
__global__ void __launch_bounds__(256, 2) k_ctx(float* __restrict__ out) {
    gemm_body(3, g_Ph, g_Pl, g_Vth, g_Vtl, nullptr, out, nullptr, nullptr, SQ,
              HD, 1.f);
}

union F4 { float4 v; float f[4]; };

__global__ void __launch_bounds__(256) softmax_kernel() {
    const int row = blockIdx.x;
    const float* p = g_S + (size_t)row * SQ;
    const int tid = threadIdx.x;

    F4 v[4];
#pragma unroll
    for (int i = 0; i < 4; i++)
        v[i].v = *(const float4*)(p + tid * 4 + i * 1024);

    __shared__ float red[8];
    float m = -1e30f;
#pragma unroll
    for (int i = 0; i < 4; i++)
#pragma unroll
        for (int j = 0; j < 4; j++) m = fmaxf(m, v[i].f[j]);
#pragma unroll
    for (int o = 16; o > 0; o >>= 1)
        m = fmaxf(m, __shfl_xor_sync(0xffffffffu, m, o));
    if ((tid & 31) == 0) red[tid >> 5] = m;
    __syncthreads();
    float bm = red[0];
#pragma unroll
    for (int w = 1; w < 8; w++) bm = fmaxf(bm, red[w]);

    float s = 0.0f;
#pragma unroll
    for (int i = 0; i < 4; i++)
#pragma unroll
        for (int j = 0; j < 4; j++) {
            const float e = __expf(v[i].f[j] - bm);
            v[i].f[j] = e;
            s += e;
        }
#pragma unroll
    for (int o = 16; o > 0; o >>= 1) s += __shfl_xor_sync(0xffffffffu, s, o);
    __syncthreads();
    if ((tid & 31) == 0) red[tid >> 5] = s;
    __syncthreads();
    float bs = 0.0f;
#pragma unroll
    for (int w = 0; w < 8; w++) bs += red[w];
    const float inv = 1.0f / bs;

    const size_t base = (size_t)row * SQ;
#pragma unroll
    for (int i = 0; i < 4; i++) {
        uint32_t h0, l0, h1, l1;
        split_pack2(v[i].f[0] * inv, v[i].f[1] * inv, h0, l0);
        split_pack2(v[i].f[2] * inv, v[i].f[3] * inv, h1, l1);
        const size_t idx = base + tid * 4 + i * 1024;
        *(uint2*)(g_Ph + idx) = make_uint2(h0, h1);
        *(uint2*)(g_Pl + idx) = make_uint2(l0, l1);
    }
}

// ------------------------------ launcher -----------------------------------

extern "C" void kernel_launch(void* const* d_in, const int* in_sizes, int n_in,
                              void* d_out, int out_size) {
    const float* q = (const float*)d_in[0];
    const float* k = (const float*)d_in[1];
    const float* v = (const float*)d_in[2];
    const float* Wq = (const float*)d_in[3];
    const float* bq = (const float*)d_in[4];
    const float* Wk = (const float*)d_in[5];
    const float* bk = (const float*)d_in[6];
    const float* Wv = (const float*)d_in[7];
    const float* bv = (const float*)d_in[8];

    cudaFuncSetAttribute(k_proj_all,
                         cudaFuncAttributeMaxDynamicSharedMemorySize, SMEM_DYN);
    cudaFuncSetAttribute(k_scores, cudaFuncAttributeMaxDynamicSharedMemorySize,
                         SMEM_DYN);
    cudaFuncSetAttribute(k_ctx, cudaFuncAttributeMaxDynamicSharedMemorySize,
                         SMEM_DYN);

    conv_in<<<(SQ * DI / 4) / 256, 256>>>((const float4*)q, (const float4*)k,
                                          (const float4*)v);
    conv_w<<<dim3(HD / 32, DI / 32, 3), dim3(32, 8)>>>(Wq, Wk, Wv);

    k_proj_all<<<dim3(HD / 128, SQ / 128, 3), 256, SMEM_DYN>>>(bq, bk, bv);

    k_scores<<<dim3(SQ / 128, SQ / 128), 256, SMEM_DYN>>>();
    softmax_kernel<<<SQ, 256>>>();
    k_ctx<<<dim3(HD / 128, SQ / 128), 256, SMEM_DYN>>>((float*)d_out);
}